// round 1
// baseline (speedup 1.0000x reference)
#include <cuda_runtime.h>

#define EN       262144
#define Dm       128
#define Hm       512
#define ROWS     32
#define NTHREADS 256
#define CHUNK    256   // H processed in 2 chunks of 256

typedef unsigned long long ull;

// packed fp32x2 FMA (SASS FFMA2) — 2 FMAs per issue slot
__device__ __forceinline__ ull f2fma(ull a, ull b, ull c) {
    ull d;
    asm("fma.rn.f32x2 %0, %1, %2, %3;" : "=l"(d) : "l"(a), "l"(b), "l"(c));
    return d;
}
__device__ __forceinline__ ull f2pack(float x, float y) {
    ull d;
    asm("mov.b64 %0, {%1, %2};" : "=l"(d) : "f"(x), "f"(y));
    return d;
}
__device__ __forceinline__ float2 f2unpack(ull v) {
    float2 r;
    asm("mov.b64 {%0, %1}, %2;" : "=f"(r.x), "=f"(r.y) : "l"(v));
    return r;
}

__global__ void __launch_bounds__(NTHREADS, 2) edge_mlp_kernel(
    const float* __restrict__ x_i, const float* __restrict__ x_j,
    const float* __restrict__ edge,
    const float* __restrict__ W1, const float* __restrict__ b1,
    const float* __restrict__ W2, const float* __restrict__ b2,
    const float* __restrict__ gamma, const float* __restrict__ beta,
    float* __restrict__ out)
{
    __shared__ float sbuf[ROWS * CHUNK];   // 32 KB SiLU staging (one H-chunk)

    const int tid = threadIdx.x;
    const int tx  = tid & 31;   // lane: owns output cols 4*tx..4*tx+3
    const int ty  = tid >> 5;   // warp: owns rows ty, ty+8, ty+16, ty+24
    const int row0 = blockIdx.x * ROWS;

    // ---- output accumulators: 4 rows x 4 cols (2 f32x2 pairs), init = b2 ----
    ull accO[4][2];
    {
        float4 b2v = reinterpret_cast<const float4*>(b2)[tx];
        ull p0 = f2pack(b2v.x, b2v.y), p1 = f2pack(b2v.z, b2v.w);
#pragma unroll
        for (int i = 0; i < 4; i++) { accO[i][0] = p0; accO[i][1] = p1; }
    }

#pragma unroll 1
    for (int ch = 0; ch < 2; ch++) {
        const int c0   = ch * CHUNK;
        const int coff = c0 + 8 * tx;       // this thread's 8 hidden cols

        // ---- GEMM1 accumulators: 4 rows x 8 cols (4 pairs), init = b1 ----
        ull acc1[4][4];
        {
            float4 ba = *reinterpret_cast<const float4*>(b1 + coff);
            float4 bb = *reinterpret_cast<const float4*>(b1 + coff + 4);
            ull p0 = f2pack(ba.x, ba.y), p1 = f2pack(ba.z, ba.w);
            ull p2 = f2pack(bb.x, bb.y), p3 = f2pack(bb.z, bb.w);
#pragma unroll
            for (int i = 0; i < 4; i++) {
                acc1[i][0] = p0; acc1[i][1] = p1; acc1[i][2] = p2; acc1[i][3] = p3;
            }
        }

        // ---- GEMM1: K=384 = 3 segments (x_i | x_j | edge_attr) of 128 ----
#pragma unroll 1
        for (int seg = 0; seg < 3; seg++) {
            const float* xs = (seg == 0) ? x_i : (seg == 1) ? x_j : edge;
#pragma unroll 4
            for (int k4 = 0; k4 < 128; k4 += 4) {
                float4 xv[4];
#pragma unroll
                for (int i = 0; i < 4; i++) {
                    int r = row0 + ty + 8 * i;
                    xv[i] = *reinterpret_cast<const float4*>(xs + (size_t)r * Dm + k4);
                }
#pragma unroll
                for (int kk = 0; kk < 4; kk++) {
                    const float* wr = W1 + (size_t)(seg * 128 + k4 + kk) * Hm + coff;
                    ulonglong2 wa = *reinterpret_cast<const ulonglong2*>(wr);
                    ulonglong2 wb = *reinterpret_cast<const ulonglong2*>(wr + 4);
#pragma unroll
                    for (int i = 0; i < 4; i++) {
                        float x = (kk == 0) ? xv[i].x : (kk == 1) ? xv[i].y
                                : (kk == 2) ? xv[i].z : xv[i].w;
                        ull xd = f2pack(x, x);
                        acc1[i][0] = f2fma(xd, wa.x, acc1[i][0]);
                        acc1[i][1] = f2fma(xd, wa.y, acc1[i][1]);
                        acc1[i][2] = f2fma(xd, wb.x, acc1[i][2]);
                        acc1[i][3] = f2fma(xd, wb.y, acc1[i][3]);
                    }
                }
            }
        }

        __syncthreads();   // previous chunk's GEMM2 done reading sbuf

        // ---- SiLU -> smem staging ----
#pragma unroll
        for (int i = 0; i < 4; i++) {
            int r = ty + 8 * i;
            float v[8];
#pragma unroll
            for (int p = 0; p < 4; p++) {
                float2 u = f2unpack(acc1[i][p]);
                v[2 * p] = u.x; v[2 * p + 1] = u.y;
            }
#pragma unroll
            for (int q = 0; q < 8; q++)
                v[q] = v[q] / (1.0f + __expf(-v[q]));
            float4* dst = reinterpret_cast<float4*>(sbuf + r * CHUNK + 8 * tx);
            dst[0] = make_float4(v[0], v[1], v[2], v[3]);
            dst[1] = make_float4(v[4], v[5], v[6], v[7]);
        }
        __syncthreads();

        // ---- GEMM2 partial: out += silu_chunk @ W2[c0:c0+256, :] ----
#pragma unroll 4
        for (int j4 = 0; j4 < CHUNK; j4 += 4) {
            float4 hv[4];
#pragma unroll
            for (int i = 0; i < 4; i++)
                hv[i] = *reinterpret_cast<const float4*>(sbuf + (ty + 8 * i) * CHUNK + j4);
#pragma unroll
            for (int kk = 0; kk < 4; kk++) {
                const float* wr = W2 + (size_t)(c0 + j4 + kk) * Dm + 4 * tx;
                ulonglong2 w = *reinterpret_cast<const ulonglong2*>(wr);
#pragma unroll
                for (int i = 0; i < 4; i++) {
                    float h = (kk == 0) ? hv[i].x : (kk == 1) ? hv[i].y
                            : (kk == 2) ? hv[i].z : hv[i].w;
                    ull hd = f2pack(h, h);
                    accO[i][0] = f2fma(hd, w.x, accO[i][0]);
                    accO[i][1] = f2fma(hd, w.y, accO[i][1]);
                }
            }
        }
    }

    // ---- LayerNorm (warp-shuffle row reduction) + residual + store ----
    float4 g  = reinterpret_cast<const float4*>(gamma)[tx];
    float4 bt = reinterpret_cast<const float4*>(beta)[tx];
#pragma unroll
    for (int i = 0; i < 4; i++) {
        float2 u0 = f2unpack(accO[i][0]), u1 = f2unpack(accO[i][1]);
        float v0 = u0.x, v1 = u0.y, v2 = u1.x, v3 = u1.y;

        float s = v0 + v1 + v2 + v3;
#pragma unroll
        for (int o = 16; o > 0; o >>= 1) s += __shfl_xor_sync(0xffffffffu, s, o);
        float mu = s * (1.0f / 128.0f);

        float d0 = v0 - mu, d1 = v1 - mu, d2 = v2 - mu, d3 = v3 - mu;
        float q = d0 * d0 + d1 * d1 + d2 * d2 + d3 * d3;
#pragma unroll
        for (int o = 16; o > 0; o >>= 1) q += __shfl_xor_sync(0xffffffffu, q, o);
        float rs = rsqrtf(q * (1.0f / 128.0f) + 1e-5f);

        int gr = row0 + ty + 8 * i;
        float4 e = reinterpret_cast<const float4*>(edge)[(size_t)gr * 32 + tx];
        float4 o4;
        o4.x = d0 * rs * g.x + bt.x + e.x;
        o4.y = d1 * rs * g.y + bt.y + e.y;
        o4.z = d2 * rs * g.z + bt.z + e.z;
        o4.w = d3 * rs * g.w + bt.w + e.w;
        reinterpret_cast<float4*>(out)[(size_t)gr * 32 + tx] = o4;
    }
}

extern "C" void kernel_launch(void* const* d_in, const int* in_sizes, int n_in,
                              void* d_out, int out_size)
{
    const float* x_i   = (const float*)d_in[0];
    const float* x_j   = (const float*)d_in[1];
    const float* edge  = (const float*)d_in[2];
    const float* W1    = (const float*)d_in[3];
    const float* b1    = (const float*)d_in[4];
    const float* W2    = (const float*)d_in[5];
    const float* b2    = (const float*)d_in[6];
    const float* gamma = (const float*)d_in[7];
    const float* beta  = (const float*)d_in[8];
    float* out = (float*)d_out;

    edge_mlp_kernel<<<EN / ROWS, NTHREADS>>>(x_i, x_j, edge, W1, b1, W2, b2,
                                             gamma, beta, out);
}

// round 3
// speedup vs baseline: 1.9353x; 1.9353x over previous
#include <cuda_runtime.h>
#include <cuda_bf16.h>
#include <cstdint>

#define EN    262144
#define NCTA  2048          // 128 rows per CTA
#define NTH   512

// ---------- frag-packed weights (filled once by pack kernels) ----------
// W1: 24 tiles (chunk*6+slice), tile = [64k x 128n]: hi 16KB + lo 16KB = 32KB
//     entry: ((kt*16+nt)*32+lane)*8 + reg*4
__device__ __align__(128) unsigned char g_W1p[24 * 32768];   // 768 KB
// W2: 8 tiles (chunk*2+kslice), same 32KB format
__device__ __align__(128) unsigned char g_W2p[8 * 32768];    // 256 KB

// ---------- smem layout ----------
#define SM_A0   1024        // A slice frag buf 0: hi 16KB + lo 16KB
#define SM_A1   33792
#define SM_W10  66560       // W1 slice buf 0 (32KB)
#define SM_W11  99328
#define SM_W2   132096      // W2 chunk (2 slices, 64KB)
#define SM_H    197632      // h slice frag buf (32KB)
#define SM_TOT  230400

// ---------- PTX helpers ----------
__device__ __forceinline__ uint32_t smem_u32(const void* p) {
    uint32_t a;
    asm("{ .reg .u64 t; cvta.to.shared.u64 t, %1; cvt.u32.u64 %0, t; }" : "=r"(a) : "l"(p));
    return a;
}
#define MBAR_INIT(a, n)   asm volatile("mbarrier.init.shared.b64 [%0], %1;" :: "r"(a), "r"(n) : "memory")
#define MBAR_EXPECT(a, b) asm volatile("mbarrier.arrive.expect_tx.shared.b64 _, [%0], %1;" :: "r"(a), "r"(b) : "memory")
#define MBAR_WAIT(a, ph) do { \
    uint32_t _m = (a), _p = (ph), _d; \
    asm volatile("{ .reg .pred p; mbarrier.try_wait.parity.acquire.cta.shared::cta.b64 p, [%1], %2; selp.b32 %0,1,0,p; }" \
        : "=r"(_d) : "r"(_m), "r"(_p) : "memory"); \
    if (!_d) { \
        asm volatile("{ .reg .pred P1; WL_%=: mbarrier.try_wait.parity.acquire.cta.shared::cta.b64 P1, [%0], %1, 0x989680;\n\t" \
                     "@P1 bra.uni WD_%=; bra.uni WL_%=; WD_%=: }" :: "r"(_m), "r"(_p) : "memory"); \
    } } while (0)

__device__ __forceinline__ void bulk_g2s(uint32_t dst, const void* src, uint32_t bytes, uint32_t bar) {
    asm volatile("cp.async.bulk.shared::cluster.global.mbarrier::complete_tx::bytes [%0], [%1], %2, [%3];"
        :: "r"(dst), "l"(src), "r"(bytes), "r"(bar) : "memory");
}
// pack two fp32 -> bf16x2, v0 in LOWER half (lower k index)
__device__ __forceinline__ uint32_t pack2(float v0, float v1) {
    uint32_t r;
    asm("cvt.rn.bf16x2.f32 %0, %1, %2;" : "=r"(r) : "f"(v1), "f"(v0));
    return r;
}
__device__ __forceinline__ void mma_bf16(float* c, const uint4& a, const uint2& b) {
    asm volatile("mma.sync.aligned.m16n8k16.row.col.f32.bf16.bf16.f32 "
        "{%0,%1,%2,%3}, {%4,%5,%6,%7}, {%8,%9}, {%0,%1,%2,%3};"
        : "+f"(c[0]), "+f"(c[1]), "+f"(c[2]), "+f"(c[3])
        : "r"(a.x), "r"(a.y), "r"(a.z), "r"(a.w), "r"(b.x), "r"(b.y));
}

// ---------- pack kernels (frag-order weights, hi/lo bf16) ----------
__global__ void pack_w1(const float* __restrict__ W1) {
    int idx = blockIdx.x * blockDim.x + threadIdx.x;   // kp*512 + n
    if (idx >= 192 * 512) return;
    int kp = idx >> 9, n = idx & 511, k = kp * 2;
    float v0 = W1[(size_t)k * 512 + n], v1 = W1[(size_t)(k + 1) * 512 + n];
    __nv_bfloat16 h0 = __float2bfloat16(v0), h1 = __float2bfloat16(v1);
    uint32_t hi = pack2(v0, v1);
    uint32_t lo = pack2(v0 - __bfloat162float(h0), v1 - __bfloat162float(h1));
    int chunk = n >> 7, slice = k >> 6;
    int kt = (k & 63) >> 4, kr = k & 15, reg = kr >> 3, nt = (n & 127) >> 3;
    int lane = (n & 7) * 4 + ((kr & 7) >> 1);
    size_t off = (size_t)(chunk * 6 + slice) * 32768 + (size_t)((kt * 16 + nt) * 32 + lane) * 8 + reg * 4;
    *(uint32_t*)(g_W1p + off)         = hi;
    *(uint32_t*)(g_W1p + off + 16384) = lo;
}
__global__ void pack_w2(const float* __restrict__ W2) {
    int idx = blockIdx.x * blockDim.x + threadIdx.x;   // kp*128 + n
    if (idx >= 256 * 128) return;
    int kp = idx >> 7, n = idx & 127, k = kp * 2;
    float v0 = W2[(size_t)k * 128 + n], v1 = W2[(size_t)(k + 1) * 128 + n];
    __nv_bfloat16 h0 = __float2bfloat16(v0), h1 = __float2bfloat16(v1);
    uint32_t hi = pack2(v0, v1);
    uint32_t lo = pack2(v0 - __bfloat162float(h0), v1 - __bfloat162float(h1));
    int chunk = k >> 7, ksl = (k >> 6) & 1;
    int kt = (k & 63) >> 4, kr = k & 15, reg = kr >> 3, nt = n >> 3;
    int lane = (n & 7) * 4 + ((kr & 7) >> 1);
    size_t off = (size_t)(chunk * 2 + ksl) * 32768 + (size_t)((kt * 16 + nt) * 32 + lane) * 8 + reg * 4;
    *(uint32_t*)(g_W2p + off)         = hi;
    *(uint32_t*)(g_W2p + off + 16384) = lo;
}

// ---------- main kernel ----------
__global__ void __launch_bounds__(NTH, 1) edge_mlp_hmma(
    const float* __restrict__ x_i, const float* __restrict__ x_j,
    const float* __restrict__ edge,
    const float* __restrict__ b1, const float* __restrict__ b2,
    const float* __restrict__ gamma, const float* __restrict__ beta,
    float* __restrict__ out)
{
    extern __shared__ char smem[];
    const uint32_t sb = smem_u32(smem);
    const int tid  = threadIdx.x;
    const int w    = tid >> 5, lane = tid & 31;
    const int mband = w >> 2, nband = w & 3;
    const int row0 = blockIdx.x * 128;

    if (tid == 0) { MBAR_INIT(sb + 0, 1); MBAR_INIT(sb + 8, 1); MBAR_INIT(sb + 16, 1); }
    __syncthreads();

    float acc1[2][4][4];
    float acc2[2][4][4];
#pragma unroll
    for (int a = 0; a < 2; a++)
#pragma unroll
        for (int b = 0; b < 4; b++)
#pragma unroll
            for (int cc = 0; cc < 4; cc++) { acc1[a][b][cc] = 0.f; acc2[a][b][cc] = 0.f; }

    // A-conversion thread constants: thread covers row convR, k quarter convKQ..+15
    const int convR  = tid >> 2;          // 0..127
    const int convKQ = (tid & 3) * 16;
    const int cmt = convR >> 4, crr = convR & 15, ckt = tid & 3;
    const uint32_t cbase = (uint32_t)((cmt * 4 + ckt) * 32) * 16;   // + lane_a*16 + reg*4

    int p0 = 0, p1 = 0, pw = 0;

    // prologue: W1 tile 0 copy + convert A slice 0 into buf0
    if (tid == 0) { MBAR_EXPECT(sb + 0, 32768); bulk_g2s(sb + SM_A0 - SM_A0 + SM_W10, g_W1p, 32768, sb + 0); }
    {
        const float* xs = x_i;
        float4 xr[4];
#pragma unroll
        for (int j = 0; j < 4; j++)
            xr[j] = *(const float4*)(xs + (size_t)(row0 + convR) * 128 + convKQ + 4 * j);
#pragma unroll
        for (int i = 0; i < 8; i++) {
            float v0 = (i & 1) ? ((i >> 1) == 0 ? xr[0].z : (i >> 1) == 1 ? xr[1].z : (i >> 1) == 2 ? xr[2].z : xr[3].z)
                               : ((i >> 1) == 0 ? xr[0].x : (i >> 1) == 1 ? xr[1].x : (i >> 1) == 2 ? xr[2].x : xr[3].x);
            float v1 = (i & 1) ? ((i >> 1) == 0 ? xr[0].w : (i >> 1) == 1 ? xr[1].w : (i >> 1) == 2 ? xr[2].w : xr[3].w)
                               : ((i >> 1) == 0 ? xr[0].y : (i >> 1) == 1 ? xr[1].y : (i >> 1) == 2 ? xr[2].y : xr[3].y);
            __nv_bfloat16 h0 = __float2bfloat16(v0), h1 = __float2bfloat16(v1);
            uint32_t hi = pack2(v0, v1);
            uint32_t lo = pack2(v0 - __bfloat162float(h0), v1 - __bfloat162float(h1));
            int reg = (crr >> 3) + 2 * (i >> 2);
            int la  = (crr & 7) * 4 + (i & 3);
            uint32_t off = cbase + (uint32_t)la * 16 + reg * 4;
            *(uint32_t*)(smem + SM_A0 + off)         = hi;
            *(uint32_t*)(smem + SM_A0 + 16384 + off) = lo;
        }
    }
    __syncthreads();

#pragma unroll 1
    for (int c = 0; c < 4; c++) {
        // W2 chunk prefetch (64KB)
        if (tid == 0) { MBAR_EXPECT(sb + 16, 65536); bulk_g2s(sb + SM_W2, g_W2p + (size_t)c * 65536, 65536, sb + 16); }

        // ===== GEMM1: 6 k-slices of 64 =====
#pragma unroll 1
        for (int sl = 0; sl < 6; sl++) {
            const int s = c * 6 + sl;
            // issue next W1 tile copy
            if (tid == 0 && s < 23) {
                uint32_t bar = sb + (((s + 1) & 1) ? 8 : 0);
                uint32_t dst = sb + (((s + 1) & 1) ? SM_W11 : SM_W10);
                MBAR_EXPECT(bar, 32768);
                bulk_g2s(dst, g_W1p + (size_t)(s + 1) * 32768, 32768, bar);
            }
            // prefetch x regs for slice s+1
            float4 xr[4];
            int sl2 = (s + 1) % 6;
            if (s < 23) {
                const float* xs = (sl2 < 2) ? x_i : (sl2 < 4) ? x_j : edge;
                int koff = (sl2 & 1) * 64;
#pragma unroll
                for (int j = 0; j < 4; j++)
                    xr[j] = *(const float4*)(xs + (size_t)(row0 + convR) * 128 + koff + convKQ + 4 * j);
            }
            // wait W1 slice s
            if (s & 1) { MBAR_WAIT(sb + 8, p1); p1 ^= 1; }
            else       { MBAR_WAIT(sb + 0, p0); p0 ^= 1; }

            const char* Ab = smem + ((s & 1) ? SM_A1 : SM_A0);
            const char* Wb = smem + ((s & 1) ? SM_W11 : SM_W10);
            // MMA over 4 k-steps
#pragma unroll
            for (int kt = 0; kt < 4; kt++) {
                uint4 ah[2], al[2];
#pragma unroll
                for (int m = 0; m < 2; m++) {
                    uint32_t aoff = (uint32_t)(((mband * 2 + m) * 4 + kt) * 32 + lane) * 16;
                    ah[m] = *(const uint4*)(Ab + aoff);
                    al[m] = *(const uint4*)(Ab + 16384 + aoff);
                }
#pragma unroll
                for (int ntp = 0; ntp < 4; ntp++) {
                    int nt = nband * 4 + ntp;
                    uint32_t boff = (uint32_t)((kt * 16 + nt) * 32 + lane) * 8;
                    uint2 bh = *(const uint2*)(Wb + boff);
                    uint2 bl = *(const uint2*)(Wb + 16384 + boff);
                    mma_bf16(acc1[0][ntp], ah[0], bh);
                    mma_bf16(acc1[0][ntp], ah[0], bl);
                    mma_bf16(acc1[0][ntp], al[0], bh);
                    mma_bf16(acc1[1][ntp], ah[1], bh);
                    mma_bf16(acc1[1][ntp], ah[1], bl);
                    mma_bf16(acc1[1][ntp], al[1], bh);
                }
            }
            // convert x slice s+1 into other A buffer
            if (s < 23) {
                char* Ab2 = smem + (((s + 1) & 1) ? SM_A1 : SM_A0);
#pragma unroll
                for (int i = 0; i < 8; i++) {
                    float v0, v1;
                    switch (i >> 1) {
                        case 0: v0 = (i & 1) ? xr[0].z : xr[0].x; v1 = (i & 1) ? xr[0].w : xr[0].y; break;
                        case 1: v0 = (i & 1) ? xr[1].z : xr[1].x; v1 = (i & 1) ? xr[1].w : xr[1].y; break;
                        case 2: v0 = (i & 1) ? xr[2].z : xr[2].x; v1 = (i & 1) ? xr[2].w : xr[2].y; break;
                        default:v0 = (i & 1) ? xr[3].z : xr[3].x; v1 = (i & 1) ? xr[3].w : xr[3].y; break;
                    }
                    __nv_bfloat16 h0 = __float2bfloat16(v0), h1 = __float2bfloat16(v1);
                    uint32_t hi = pack2(v0, v1);
                    uint32_t lo = pack2(v0 - __bfloat162float(h0), v1 - __bfloat162float(h1));
                    int reg = (crr >> 3) + 2 * (i >> 2);
                    int la  = (crr & 7) * 4 + (i & 3);
                    uint32_t off = cbase + (uint32_t)la * 16 + reg * 4;
                    *(uint32_t*)(Ab2 + off)         = hi;
                    *(uint32_t*)(Ab2 + 16384 + off) = lo;
                }
            }
            __syncthreads();
        }

        // ===== SiLU -> h frags; GEMM2 over 2 k-slices of 64 =====
#pragma unroll 1
        for (int ksl = 0; ksl < 2; ksl++) {
            if ((nband >> 1) == ksl) {
#pragma unroll
                for (int ntp = 0; ntp < 4; ntp++) {
                    int colc = nband * 32 + ntp * 8 + (lane & 3) * 2;  // within-chunk col
                    int colg = c * 128 + colc;
                    float bb0 = b1[colg], bb1 = b1[colg + 1];
                    int kloc = colc - ksl * 64;
                    int kt_h = kloc >> 4;
                    int regb = 2 * ((kloc >> 3) & 1);
#pragma unroll
                    for (int mtp = 0; mtp < 2; mtp++) {
                        uint32_t base = (uint32_t)(((mband * 2 + mtp) * 4 + kt_h) * 32 + lane) * 16;
                        // rows lane/4 and lane/4+8
#pragma unroll
                        for (int hh = 0; hh < 2; hh++) {
                            float v0 = acc1[mtp][ntp][hh * 2]     + bb0;
                            float v1 = acc1[mtp][ntp][hh * 2 + 1] + bb1;
                            v0 = v0 / (1.0f + __expf(-v0));
                            v1 = v1 / (1.0f + __expf(-v1));
                            __nv_bfloat16 h0 = __float2bfloat16(v0), h1 = __float2bfloat16(v1);
                            uint32_t hi = pack2(v0, v1);
                            uint32_t lo = pack2(v0 - __bfloat162float(h0), v1 - __bfloat162float(h1));
                            uint32_t off = base + (uint32_t)(regb + hh) * 4;
                            *(uint32_t*)(smem + SM_H + off)         = hi;
                            *(uint32_t*)(smem + SM_H + 16384 + off) = lo;
                        }
                    }
                }
            }
            if (ksl == 0) { MBAR_WAIT(sb + 16, pw); pw ^= 1; }
            __syncthreads();

            const char* Hb  = smem + SM_H;
            const char* W2b = smem + SM_W2 + ksl * 32768;
#pragma unroll
            for (int kt = 0; kt < 4; kt++) {
                uint4 ah[2], al[2];
#pragma unroll
                for (int m = 0; m < 2; m++) {
                    uint32_t aoff = (uint32_t)(((mband * 2 + m) * 4 + kt) * 32 + lane) * 16;
                    ah[m] = *(const uint4*)(Hb + aoff);
                    al[m] = *(const uint4*)(Hb + 16384 + aoff);
                }
#pragma unroll
                for (int ntp = 0; ntp < 4; ntp++) {
                    int nt = nband * 4 + ntp;
                    uint32_t boff = (uint32_t)((kt * 16 + nt) * 32 + lane) * 8;
                    uint2 bh = *(const uint2*)(W2b + boff);
                    uint2 bl = *(const uint2*)(W2b + 16384 + boff);
                    mma_bf16(acc2[0][ntp], ah[0], bh);
                    mma_bf16(acc2[0][ntp], ah[0], bl);
                    mma_bf16(acc2[0][ntp], al[0], bh);
                    mma_bf16(acc2[1][ntp], ah[1], bh);
                    mma_bf16(acc2[1][ntp], ah[1], bl);
                    mma_bf16(acc2[1][ntp], al[1], bh);
                }
            }
            __syncthreads();
        }
        // reset acc1 for next chunk
#pragma unroll
        for (int a = 0; a < 2; a++)
#pragma unroll
            for (int b = 0; b < 4; b++)
#pragma unroll
                for (int cc = 0; cc < 4; cc++) acc1[a][b][cc] = 0.f;
    }

    // ===== epilogue: stage acc2+b2, LayerNorm, +edge, store =====
    float* stg = (float*)(smem + SM_A0);   // 128 x 130 fp32 = 66560B (A/W1 areas dead)
    __syncthreads();
#pragma unroll
    for (int ntp = 0; ntp < 4; ntp++) {
        int col = nband * 32 + ntp * 8 + (lane & 3) * 2;
        float bb0 = b2[col], bb1 = b2[col + 1];
#pragma unroll
        for (int mtp = 0; mtp < 2; mtp++) {
            int row = mband * 32 + mtp * 16 + (lane >> 2);
            float2 v0 = make_float2(acc2[mtp][ntp][0] + bb0, acc2[mtp][ntp][1] + bb1);
            float2 v1 = make_float2(acc2[mtp][ntp][2] + bb0, acc2[mtp][ntp][3] + bb1);
            *(float2*)(stg + row * 130 + col)       = v0;
            *(float2*)(stg + (row + 8) * 130 + col) = v1;
        }
    }
    __syncthreads();
    if (tid < 128) {
        float* rp = stg + tid * 130;
        float s = 0.f, q = 0.f;
#pragma unroll
        for (int j = 0; j < 128; j += 2) {
            float2 v = *(float2*)(rp + j);
            s += v.x + v.y;
            q += v.x * v.x + v.y * v.y;
        }
        float mu = s * (1.0f / 128.0f);
        float var = q * (1.0f / 128.0f) - mu * mu;
        float rs = rsqrtf(var + 1e-5f);
#pragma unroll
        for (int j = 0; j < 128; j += 2) {
            float2 v = *(float2*)(rp + j);
            float2 g = *(const float2*)(gamma + j);
            float2 b = *(const float2*)(beta + j);
            v.x = (v.x - mu) * rs * g.x + b.x;
            v.y = (v.y - mu) * rs * g.y + b.y;
            *(float2*)(rp + j) = v;
        }
    }
    __syncthreads();
#pragma unroll
    for (int it = 0; it < 8; it++) {
        int idx = tid + it * NTH;
        int r = idx >> 5, c4 = idx & 31;
        float2 u0 = *(float2*)(stg + r * 130 + c4 * 4);
        float2 u1 = *(float2*)(stg + r * 130 + c4 * 4 + 2);
        float4 e = *(const float4*)(edge + (size_t)(row0 + r) * 128 + c4 * 4);
        float4 o = make_float4(u0.x + e.x, u0.y + e.y, u1.x + e.z, u1.y + e.w);
        *(float4*)(out + (size_t)(row0 + r) * 128 + c4 * 4) = o;
    }
}

extern "C" void kernel_launch(void* const* d_in, const int* in_sizes, int n_in,
                              void* d_out, int out_size)
{
    const float* x_i   = (const float*)d_in[0];
    const float* x_j   = (const float*)d_in[1];
    const float* edge  = (const float*)d_in[2];
    const float* W1    = (const float*)d_in[3];
    const float* b1    = (const float*)d_in[4];
    const float* W2    = (const float*)d_in[5];
    const float* b2    = (const float*)d_in[6];
    const float* gamma = (const float*)d_in[7];
    const float* beta  = (const float*)d_in[8];
    float* out = (float*)d_out;

    cudaFuncSetAttribute(edge_mlp_hmma, cudaFuncAttributeMaxDynamicSharedMemorySize, SM_TOT);

    pack_w1<<<(192 * 512 + 255) / 256, 256>>>(W1);
    pack_w2<<<(256 * 128 + 255) / 256, 256>>>(W2);
    edge_mlp_hmma<<<NCTA, NTH, SM_TOT>>>(x_i, x_j, edge, b1, b2, gamma, beta, out);
}

// round 4
// speedup vs baseline: 2.0323x; 1.0501x over previous
#include <cuda_runtime.h>
#include <cuda_bf16.h>
#include <cstdint>

#define EN    262144
#define NCTA  2048          // 128 rows per CTA
#define NTH   512

// ---------- frag-packed weights (filled once by pack kernels) ----------
// W1: 24 tiles (chunk*6+slice), tile=[64k x 128n]: entry 16B = {hi.reg0,hi.reg1,lo.reg0,lo.reg1}
__device__ __align__(128) unsigned char g_W1p[24 * 32768];   // 768 KB
// W2: 8 tiles (chunk*2+kslice), same format
__device__ __align__(128) unsigned char g_W2p[8 * 32768];    // 256 KB

// ---------- smem layout ----------
#define SM_A0   1024        // A frag buf 0: hi 16KB + lo 16KB
#define SM_A1   33792
#define SM_W10  66560
#define SM_W11  99328
#define SM_W2   132096      // W2 chunk (2 k-slices, 64KB)
#define SM_XS   197632      // xstage (GEMM1) / H-frag (GEMM2) overlay, 32KB
#define SM_TOT  230400

#define SW128(o) ((o) ^ (((o) >> 3) & 0x70))

// ---------- PTX helpers ----------
__device__ __forceinline__ uint32_t smem_u32(const void* p) {
    uint32_t a;
    asm("{ .reg .u64 t; cvta.to.shared.u64 t, %1; cvt.u32.u64 %0, t; }" : "=r"(a) : "l"(p));
    return a;
}
#define MBAR_INIT(a, n)   asm volatile("mbarrier.init.shared.b64 [%0], %1;" :: "r"(a), "r"(n) : "memory")
#define MBAR_EXPECT(a, b) asm volatile("mbarrier.arrive.expect_tx.shared.b64 _, [%0], %1;" :: "r"(a), "r"(b) : "memory")
#define MBAR_WAIT(a, ph) do { \
    uint32_t _m = (a), _p = (ph), _d; \
    asm volatile("{ .reg .pred p; mbarrier.try_wait.parity.acquire.cta.shared::cta.b64 p, [%1], %2; selp.b32 %0,1,0,p; }" \
        : "=r"(_d) : "r"(_m), "r"(_p) : "memory"); \
    if (!_d) { \
        asm volatile("{ .reg .pred P1; WL_%=: mbarrier.try_wait.parity.acquire.cta.shared::cta.b64 P1, [%0], %1, 0x989680;\n\t" \
                     "@P1 bra.uni WD_%=; bra.uni WL_%=; WD_%=: }" :: "r"(_m), "r"(_p) : "memory"); \
    } } while (0)

__device__ __forceinline__ void bulk_g2s(uint32_t dst, const void* src, uint32_t bytes, uint32_t bar) {
    asm volatile("cp.async.bulk.shared::cluster.global.mbarrier::complete_tx::bytes [%0], [%1], %2, [%3];"
        :: "r"(dst), "l"(src), "r"(bytes), "r"(bar) : "memory");
}
__device__ __forceinline__ void cpasync16(uint32_t dst, const void* src) {
    asm volatile("cp.async.cg.shared.global [%0], [%1], 16;" :: "r"(dst), "l"(src));
}
#define CP_COMMIT() asm volatile("cp.async.commit_group;" ::: "memory")
#define CP_WAIT0()  asm volatile("cp.async.wait_group 0;" ::: "memory")

// pack two fp32 -> bf16x2, v0 (lower k) in low 16 bits
__device__ __forceinline__ uint32_t pack2(float v0, float v1) {
    uint32_t r;
    asm("cvt.rn.bf16x2.f32 %0, %1, %2;" : "=r"(r) : "f"(v1), "f"(v0));
    return r;
}
__device__ __forceinline__ void mma_bf16(float* c, const uint4& a, uint32_t b0, uint32_t b1) {
    asm volatile("mma.sync.aligned.m16n8k16.row.col.f32.bf16.bf16.f32 "
        "{%0,%1,%2,%3}, {%4,%5,%6,%7}, {%8,%9}, {%0,%1,%2,%3};"
        : "+f"(c[0]), "+f"(c[1]), "+f"(c[2]), "+f"(c[3])
        : "r"(a.x), "r"(a.y), "r"(a.z), "r"(a.w), "r"(b0), "r"(b1));
}
// convert fp32 pair -> hi/lo bf16x2 and store into A-frag layout
__device__ __forceinline__ void conv_store(char* Abuf, uint32_t cbase, int crr, int i,
                                           float v0, float v1) {
    __nv_bfloat16 h0 = __float2bfloat16(v0), h1 = __float2bfloat16(v1);
    uint32_t hi = pack2(v0, v1);
    uint32_t lo = pack2(v0 - __bfloat162float(h0), v1 - __bfloat162float(h1));
    uint32_t off = cbase + (uint32_t)(((crr & 7) * 4 + (i & 3)) * 16)
                         + (uint32_t)(((crr >> 3) + 2 * (i >> 2)) * 4);
    *(uint32_t*)(Abuf + off)         = hi;
    *(uint32_t*)(Abuf + 16384 + off) = lo;
}

// ---------- pack kernels (frag-order weights, hi/lo interleaved 16B) ----------
__global__ void pack_w1(const float* __restrict__ W1) {
    int idx = blockIdx.x * blockDim.x + threadIdx.x;   // kp*512 + n
    if (idx >= 192 * 512) return;
    int kp = idx >> 9, n = idx & 511, k = kp * 2;
    float v0 = W1[(size_t)k * 512 + n], v1 = W1[(size_t)(k + 1) * 512 + n];
    __nv_bfloat16 h0 = __float2bfloat16(v0), h1 = __float2bfloat16(v1);
    uint32_t hi = pack2(v0, v1);
    uint32_t lo = pack2(v0 - __bfloat162float(h0), v1 - __bfloat162float(h1));
    int chunk = n >> 7, slice = k >> 6;
    int kt = (k & 63) >> 4, kr = k & 15, reg = kr >> 3, nt = (n & 127) >> 3;
    int lane = (n & 7) * 4 + ((kr & 7) >> 1);
    size_t off = (size_t)(chunk * 6 + slice) * 32768
               + (size_t)((kt * 16 + nt) * 32 + lane) * 16 + reg * 4;
    *(uint32_t*)(g_W1p + off)     = hi;
    *(uint32_t*)(g_W1p + off + 8) = lo;
}
__global__ void pack_w2(const float* __restrict__ W2) {
    int idx = blockIdx.x * blockDim.x + threadIdx.x;   // kp*128 + n
    if (idx >= 256 * 128) return;
    int kp = idx >> 7, n = idx & 127, k = kp * 2;
    float v0 = W2[(size_t)k * 128 + n], v1 = W2[(size_t)(k + 1) * 128 + n];
    __nv_bfloat16 h0 = __float2bfloat16(v0), h1 = __float2bfloat16(v1);
    uint32_t hi = pack2(v0, v1);
    uint32_t lo = pack2(v0 - __bfloat162float(h0), v1 - __bfloat162float(h1));
    int chunk = k >> 7, ksl = (k >> 6) & 1;
    int kt = (k & 63) >> 4, kr = k & 15, reg = kr >> 3, nt = n >> 3;
    int lane = (n & 7) * 4 + ((kr & 7) >> 1);
    size_t off = (size_t)(chunk * 2 + ksl) * 32768
               + (size_t)((kt * 16 + nt) * 32 + lane) * 16 + reg * 4;
    *(uint32_t*)(g_W2p + off)     = hi;
    *(uint32_t*)(g_W2p + off + 8) = lo;
}

// ---------- main kernel ----------
__global__ void __launch_bounds__(NTH, 1) edge_mlp_hmma(
    const float* __restrict__ x_i, const float* __restrict__ x_j,
    const float* __restrict__ edge,
    const float* __restrict__ b1, const float* __restrict__ b2,
    const float* __restrict__ gamma, const float* __restrict__ beta,
    float* __restrict__ out)
{
    extern __shared__ char smem[];
    const uint32_t sb = smem_u32(smem);
    const int tid  = threadIdx.x;
    const int w    = tid >> 5, lane = tid & 31;
    const int mband = w >> 2, nband = w & 3;
    const int row0 = blockIdx.x * 128;

    if (tid == 0) { MBAR_INIT(sb + 0, 1); MBAR_INIT(sb + 8, 1); MBAR_INIT(sb + 16, 1); }
    __syncthreads();

    float acc1[2][4][4];
    float acc2[2][4][4];
#pragma unroll
    for (int a = 0; a < 2; a++)
#pragma unroll
        for (int b = 0; b < 4; b++)
#pragma unroll
            for (int cc = 0; cc < 4; cc++) { acc1[a][b][cc] = 0.f; acc2[a][b][cc] = 0.f; }

    // conversion thread constants: row convR, k quarter q*16..q*16+15
    const int convR = tid >> 2, q = tid & 3;
    const int cmt = convR >> 4, crr = convR & 15;
    const uint32_t cbase = (uint32_t)((cmt * 4 + q) * 32) * 16;

    int p0 = 0, p1 = 0, pw = 0;

    // prologue: W1 slice0 bulk + convert slice0 (x_i, k 0..63) direct from gmem
    if (tid == 0) { MBAR_EXPECT(sb + 0, 32768); bulk_g2s(sb + SM_W10, g_W1p, 32768, sb + 0); }
    {
#pragma unroll
        for (int j = 0; j < 4; j++) {
            float4 v = *(const float4*)(x_i + (size_t)(row0 + convR) * 128 + q * 16 + 4 * j);
            conv_store(smem + SM_A0, cbase, crr, 2 * j,     v.x, v.y);
            conv_store(smem + SM_A0, cbase, crr, 2 * j + 1, v.z, v.w);
        }
    }
    __syncthreads();

#pragma unroll 1
    for (int c = 0; c < 4; c++) {
        if (tid == 0) { MBAR_EXPECT(sb + 16, 65536); bulk_g2s(sb + SM_W2, g_W2p + (size_t)c * 65536, 65536, sb + 16); }

        // ===== GEMM1: 6 k-slices of 64 =====
#pragma unroll 1
        for (int sl = 0; sl < 6; sl++) {
            const int s = c * 6 + sl;
            // W1 slice s+1 bulk into other buffer
            if (tid == 0 && s < 23) {
                uint32_t bar = sb + (((s + 1) & 1) ? 8 : 0);
                uint32_t dst = sb + (((s + 1) & 1) ? SM_W11 : SM_W10);
                MBAR_EXPECT(bar, 32768);
                bulk_g2s(dst, g_W1p + (size_t)(s + 1) * 32768, 32768, bar);
            }
            // stage raw x for slice s+1 via cp.async (no registers held)
            if (s < 23) {
                int sl2 = (s + 1) % 6;
                const float* xs = (sl2 < 2) ? x_i : (sl2 < 4) ? x_j : edge;
                int koff = (sl2 & 1) * 64;
#pragma unroll
                for (int ww = 0; ww < 4; ww++) {
                    int v = tid + ww * NTH;
                    int r = v >> 4, u = v & 15;
                    const float* src = xs + (size_t)(row0 + r) * 128 + koff + u * 4;
                    cpasync16(sb + SM_XS + SW128((uint32_t)(r * 256 + u * 16)), src);
                }
                CP_COMMIT();
            }
            // wait W1 slice s
            if (s & 1) { MBAR_WAIT(sb + 8, p1); p1 ^= 1; }
            else       { MBAR_WAIT(sb + 0, p0); p0 ^= 1; }

            const char* Ab = smem + ((s & 1) ? SM_A1 : SM_A0);
            const char* Wb = smem + ((s & 1) ? SM_W11 : SM_W10);
#pragma unroll
            for (int kt = 0; kt < 4; kt++) {
                uint4 ah[2], al[2];
#pragma unroll
                for (int m = 0; m < 2; m++) {
                    uint32_t aoff = (uint32_t)(((mband * 2 + m) * 4 + kt) * 32 + lane) * 16;
                    ah[m] = *(const uint4*)(Ab + aoff);
                    al[m] = *(const uint4*)(Ab + 16384 + aoff);
                }
#pragma unroll
                for (int ntp = 0; ntp < 4; ntp++) {
                    int nt = nband * 4 + ntp;
                    uint4 Bv = *(const uint4*)(Wb + (uint32_t)((kt * 16 + nt) * 32 + lane) * 16);
                    mma_bf16(acc1[0][ntp], ah[0], Bv.x, Bv.y);
                    mma_bf16(acc1[0][ntp], ah[0], Bv.z, Bv.w);
                    mma_bf16(acc1[0][ntp], al[0], Bv.x, Bv.y);
                    mma_bf16(acc1[1][ntp], ah[1], Bv.x, Bv.y);
                    mma_bf16(acc1[1][ntp], ah[1], Bv.z, Bv.w);
                    mma_bf16(acc1[1][ntp], al[1], Bv.x, Bv.y);
                }
            }
            CP_WAIT0();
            __syncthreads();          // staging visible to all; MMAs done
            if (s < 23) {
                char* Ab2 = smem + (((s + 1) & 1) ? SM_A1 : SM_A0);
#pragma unroll
                for (int j = 0; j < 4; j++) {
                    uint32_t ro = SM_XS + SW128((uint32_t)(convR * 256 + (q * 4 + j) * 16));
                    float4 v = *(const float4*)(smem + ro);
                    conv_store(Ab2, cbase, crr, 2 * j,     v.x, v.y);
                    conv_store(Ab2, cbase, crr, 2 * j + 1, v.z, v.w);
                }
            }
            __syncthreads();          // conversion visible before next MMA
        }

        // ===== SiLU -> h frags; GEMM2 over 2 k-slices of 64 =====
#pragma unroll 1
        for (int ksl = 0; ksl < 2; ksl++) {
            if ((nband >> 1) == ksl) {
#pragma unroll
                for (int ntp = 0; ntp < 4; ntp++) {
                    int colc = nband * 32 + ntp * 8 + (lane & 3) * 2;
                    int colg = c * 128 + colc;
                    float bb0 = b1[colg], bb1 = b1[colg + 1];
                    int kloc = colc - ksl * 64;
                    int kt_h = kloc >> 4;
                    int regb = 2 * ((kloc >> 3) & 1);
#pragma unroll
                    for (int mtp = 0; mtp < 2; mtp++) {
                        uint32_t base = (uint32_t)(((mband * 2 + mtp) * 4 + kt_h) * 32 + lane) * 16;
#pragma unroll
                        for (int hh = 0; hh < 2; hh++) {
                            float v0 = acc1[mtp][ntp][hh * 2]     + bb0;
                            float v1 = acc1[mtp][ntp][hh * 2 + 1] + bb1;
                            v0 = v0 / (1.0f + __expf(-v0));
                            v1 = v1 / (1.0f + __expf(-v1));
                            __nv_bfloat16 h0 = __float2bfloat16(v0), h1 = __float2bfloat16(v1);
                            uint32_t hi = pack2(v0, v1);
                            uint32_t lo = pack2(v0 - __bfloat162float(h0), v1 - __bfloat162float(h1));
                            uint32_t off = base + (uint32_t)(regb + hh) * 4;
                            *(uint32_t*)(smem + SM_XS + off)         = hi;
                            *(uint32_t*)(smem + SM_XS + 16384 + off) = lo;
                        }
                    }
                }
            }
            if (ksl == 0) { MBAR_WAIT(sb + 16, pw); pw ^= 1; }
            __syncthreads();

            const char* Hb  = smem + SM_XS;
            const char* W2b = smem + SM_W2 + ksl * 32768;
#pragma unroll
            for (int kt = 0; kt < 4; kt++) {
                uint4 ah[2], al[2];
#pragma unroll
                for (int m = 0; m < 2; m++) {
                    uint32_t aoff = (uint32_t)(((mband * 2 + m) * 4 + kt) * 32 + lane) * 16;
                    ah[m] = *(const uint4*)(Hb + aoff);
                    al[m] = *(const uint4*)(Hb + 16384 + aoff);
                }
#pragma unroll
                for (int ntp = 0; ntp < 4; ntp++) {
                    int nt = nband * 4 + ntp;
                    uint4 Bv = *(const uint4*)(W2b + (uint32_t)((kt * 16 + nt) * 32 + lane) * 16);
                    mma_bf16(acc2[0][ntp], ah[0], Bv.x, Bv.y);
                    mma_bf16(acc2[0][ntp], ah[0], Bv.z, Bv.w);
                    mma_bf16(acc2[0][ntp], al[0], Bv.x, Bv.y);
                    mma_bf16(acc2[1][ntp], ah[1], Bv.x, Bv.y);
                    mma_bf16(acc2[1][ntp], ah[1], Bv.z, Bv.w);
                    mma_bf16(acc2[1][ntp], al[1], Bv.x, Bv.y);
                }
            }
            __syncthreads();
        }
        // reset acc1 for next chunk
#pragma unroll
        for (int a = 0; a < 2; a++)
#pragma unroll
            for (int b = 0; b < 4; b++)
#pragma unroll
                for (int cc = 0; cc < 4; cc++) acc1[a][b][cc] = 0.f;
    }

    // ===== epilogue: stage acc2+b2, LayerNorm, +edge, store =====
    float* stg = (float*)(smem + SM_A0);   // 128 x 130 fp32 (A/W1 regions dead)
    __syncthreads();
#pragma unroll
    for (int ntp = 0; ntp < 4; ntp++) {
        int col = nband * 32 + ntp * 8 + (lane & 3) * 2;
        float bb0 = b2[col], bb1 = b2[col + 1];
#pragma unroll
        for (int mtp = 0; mtp < 2; mtp++) {
            int row = mband * 32 + mtp * 16 + (lane >> 2);
            float2 v0 = make_float2(acc2[mtp][ntp][0] + bb0, acc2[mtp][ntp][1] + bb1);
            float2 v1 = make_float2(acc2[mtp][ntp][2] + bb0, acc2[mtp][ntp][3] + bb1);
            *(float2*)(stg + row * 130 + col)       = v0;
            *(float2*)(stg + (row + 8) * 130 + col) = v1;
        }
    }
    __syncthreads();
    if (tid < 128) {
        float* rp = stg + tid * 130;
        float s = 0.f, qq = 0.f;
#pragma unroll
        for (int j = 0; j < 128; j += 2) {
            float2 v = *(float2*)(rp + j);
            s += v.x + v.y;
            qq += v.x * v.x + v.y * v.y;
        }
        float mu = s * (1.0f / 128.0f);
        float var = qq * (1.0f / 128.0f) - mu * mu;
        float rs = rsqrtf(var + 1e-5f);
#pragma unroll
        for (int j = 0; j < 128; j += 2) {
            float2 v = *(float2*)(rp + j);
            float2 g = *(const float2*)(gamma + j);
            float2 b = *(const float2*)(beta + j);
            v.x = (v.x - mu) * rs * g.x + b.x;
            v.y = (v.y - mu) * rs * g.y + b.y;
            *(float2*)(rp + j) = v;
        }
    }
    __syncthreads();
#pragma unroll
    for (int it = 0; it < 8; it++) {
        int idx = tid + it * NTH;
        int r = idx >> 5, c4 = idx & 31;
        float2 u0 = *(float2*)(stg + r * 130 + c4 * 4);
        float2 u1 = *(float2*)(stg + r * 130 + c4 * 4 + 2);
        float4 e = *(const float4*)(edge + (size_t)(row0 + r) * 128 + c4 * 4);
        float4 o = make_float4(u0.x + e.x, u0.y + e.y, u1.x + e.z, u1.y + e.w);
        *(float4*)(out + (size_t)(row0 + r) * 128 + c4 * 4) = o;
    }
}

extern "C" void kernel_launch(void* const* d_in, const int* in_sizes, int n_in,
                              void* d_out, int out_size)
{
    const float* x_i   = (const float*)d_in[0];
    const float* x_j   = (const float*)d_in[1];
    const float* edge  = (const float*)d_in[2];
    const float* W1    = (const float*)d_in[3];
    const float* b1    = (const float*)d_in[4];
    const float* W2    = (const float*)d_in[5];
    const float* b2    = (const float*)d_in[6];
    const float* gamma = (const float*)d_in[7];
    const float* beta  = (const float*)d_in[8];
    float* out = (float*)d_out;

    cudaFuncSetAttribute(edge_mlp_hmma, cudaFuncAttributeMaxDynamicSharedMemorySize, SM_TOT);

    pack_w1<<<(192 * 512 + 255) / 256, 256>>>(W1);
    pack_w2<<<(256 * 128 + 255) / 256, 256>>>(W2);
    edge_mlp_hmma<<<NCTA, NTH, SM_TOT>>>(x_i, x_j, edge, b1, b2, gamma, beta, out);
}